// round 13
// baseline (speedup 1.0000x reference)
#include <cuda_runtime.h>
#include <cuda_fp16.h>
#include <cstdint>

// FactorizedTrilinear: B=4, Z=X=C=128, D=V=2 (dv=4), IN=512, R=256
// proj: P_k[b][dv][row][eperm] = fp16( x_k[b,row,dv,:] @ W_k + b_k )
//       e stored PERMUTED within each 16-e group so tri's m16n8k16 fragment
//       halves {2t,2t+1,2t+8,2t+9} are contiguous -> single LDS.64.
// tri:  out[b,z,x,c,dv] = sum_e (p1*p2)*p3 via mma.sync.m16n8k16.f16,
//       CTA M128(4z x 32x) x N64(c), KC=128 fp16 double-buffer, 3 CTAs/SM,
//       dv-major global scratch + fused dense-float4 tail.

#define NB  4
#define NZ  128
#define NIN 512
#define NR  256
#define NDV 4

__device__ __align__(16) __half g_P1h[NB * NDV * NZ * NR];
__device__ __align__(16) __half g_P2h[NB * NDV * NZ * NR];
__device__ __align__(16) __half g_P3h[NB * NDV * NZ * NR];
// Per-CTA scratch tiles: 1024 CTAs x 32768 floats (dv-major) = 128 MB.
__device__ __align__(16) float  g_S[1024 * 32768];

__device__ __forceinline__ void cp16(uint32_t dst, const void* src) {
    asm volatile("cp.async.cg.shared.global [%0], [%1], 16;"
                 :: "r"(dst), "l"(src) : "memory");
}
__device__ __forceinline__ void cp_commit() {
    asm volatile("cp.async.commit_group;" ::: "memory");
}
template <int N>
__device__ __forceinline__ void cp_wait() {
    asm volatile("cp.async.wait_group %0;" :: "n"(N) : "memory");
}
__device__ __forceinline__ uint32_t hmul2r(uint32_t a, uint32_t b) {
    __half2 r = __hmul2(*(__half2*)&a, *(__half2*)&b);
    return *(uint32_t*)&r;
}
__device__ __forceinline__ void stg_cg_v2(float* p, float x, float y) {
    asm volatile("st.global.cg.v2.f32 [%0], {%1, %2};"
                 :: "l"(p), "f"(x), "f"(y) : "memory");
}

// ---------------------------------------------------------------------------
// Projection: grid (16, 4, 3), 256 threads, 112 KB dynamic smem.
// Block = 8 z rows (ZG), r = tid. W streamed in 16-e chunks, cp.async
// TRIPLE-buffered. All P stored fp16 with the e-permutation.
// ---------------------------------------------------------------------------
#define ZG 8
#define NCH (NIN / 16)
#define PROJ_SMEM ((ZG * NIN * NDV + 3 * 16 * NR) * 4)   // 64KB + 48KB

__global__ __launch_bounds__(256) void proj_kernel(
    const float* __restrict__ x1, const float* __restrict__ x2, const float* __restrict__ x3,
    const float* __restrict__ W1, const float* __restrict__ bb1,
    const float* __restrict__ W2, const float* __restrict__ bb2,
    const float* __restrict__ W3, const float* __restrict__ bb3)
{
    extern __shared__ __align__(16) float psm[];
    float* xs = psm;                        // [z][e][dv]  ZG*512*4 floats
    float* ws = psm + ZG * NIN * NDV;       // 3 x [e16][r] 16*256 floats each

    const int z0 = blockIdx.x * ZG;
    const int b  = blockIdx.y;
    const int k  = blockIdx.z;

    const float* x  = (k == 0) ? x1  : (k == 1) ? x2  : x3;
    const float* W  = (k == 0) ? W1  : (k == 1) ? W2  : W3;
    const float* bs = (k == 0) ? bb1 : (k == 1) ? bb2 : bb3;
    __half*      P  = (k == 0) ? g_P1h : (k == 1) ? g_P2h : g_P3h;

    const int tid = threadIdx.x;
    const uint32_t wsu = (uint32_t)__cvta_generic_to_shared(ws);

    const float* xg = x + ((size_t)(b * NZ + z0)) * NDV * NIN;
#pragma unroll
    for (int i = 0; i < ZG * 8; i++) {
        int idx = i * 256 + tid;
        int e   = idx & (NIN - 1);
        int zdv = idx >> 9;                 // 0..ZG*4-1
        xs[((zdv >> 2) * NIN + e) * NDV + (zdv & 3)] = xg[zdv * NIN + e];
    }

#define WFILL(ec_)                                                      \
    {                                                                   \
        const float4* wg = (const float4*)(W + (ec_) * 16 * NR);        \
        uint32_t base = wsu + ((ec_) % 3) * (16 * NR * 4);              \
        _Pragma("unroll")                                               \
        for (int i = 0; i < 4; i++)                                     \
            cp16(base + (i * 256 + tid) * 16, wg + i * 256 + tid);      \
    }

    float acc[ZG][NDV];
    {
        float bv = bs[tid];
#pragma unroll
        for (int z = 0; z < ZG; z++)
#pragma unroll
            for (int dv = 0; dv < NDV; dv++) acc[z][dv] = bv;
    }

    WFILL(0); cp_commit();
    WFILL(1); cp_commit();

    for (int ec = 0; ec < NCH; ec++) {
        if (ec + 2 < NCH) {
            WFILL(ec + 2);
            cp_commit();
            cp_wait<2>();
        } else if (ec + 1 < NCH) {
            cp_wait<1>();
        } else {
            cp_wait<0>();
        }
        __syncthreads();   // chunk ec visible to all (first iter covers xs too)

        const float* w = ws + (ec % 3) * 16 * NR;
#pragma unroll
        for (int e16 = 0; e16 < 16; e16++) {
            float wv = w[e16 * NR + tid];
            int e = ec * 16 + e16;
#pragma unroll
            for (int z = 0; z < ZG; z++) {
                float4 xv = *(const float4*)&xs[(z * NIN + e) * NDV];
                acc[z][0] = fmaf(xv.x, wv, acc[z][0]);
                acc[z][1] = fmaf(xv.y, wv, acc[z][1]);
                acc[z][2] = fmaf(xv.z, wv, acc[z][2]);
                acc[z][3] = fmaf(xv.w, wv, acc[z][3]);
            }
        }
        __syncthreads();   // reads of slot ec%3 done before its refill next iter
    }
#undef WFILL

    // Permuted store: within each 16-e group, half2 j -> pos 2j (j<4),
    // half2 j -> pos 2(j-4)+1 (j>=4). Fragment pairs become contiguous.
    const int e   = tid;
    const int g16 = e >> 4, loc = e & 15;
    const int h2  = loc >> 1, wlo = loc & 1;
    const int nl  = (((h2 < 4) ? (2 * h2) : (2 * (h2 - 4) + 1)) << 1) + wlo;
    const int ep  = (g16 << 4) + nl;

#pragma unroll
    for (int z = 0; z < ZG; z++)
#pragma unroll
        for (int dv = 0; dv < NDV; dv++)
            P[((size_t)((b * NDV + dv) * NZ + z0 + z)) * NR + ep] =
                __float2half_rn(acc[z][dv]);
}

// ---------------------------------------------------------------------------
// Trilinear. Grid (32, 8, 4): zq x [xq|ch] x b. CTA: M=128(4z x 32x), N=64(c).
// 8 warps = 4M x 2N; warp tile M32 x N32 (2 m-tiles x 4 n-tiles m16n8k16 f16).
// dv(4) x ck(2 x KC=128), fp16 staging double-buffered (54.4 KB, 3 CTAs/SM).
// Fragment loads are single LDS.64 thanks to the e-permutation.
// ---------------------------------------------------------------------------
#define KC    128
#define HPAD  136                         // halves per row (h2 stride 68)
#define OFF_P2H  (4 * HPAD)               // 544 halves
#define OFF_P3H  (OFF_P2H + 32 * HPAD)    // 4896 halves
#define BUF_H    (OFF_P3H + 64 * HPAD)    // 13600 halves = 27200 B
#define SMEM_BYTES (2 * BUF_H * 2)        // 54400

__global__ __launch_bounds__(256, 3) void tri_mma_kernel(float* __restrict__ out)
{
    extern __shared__ __align__(16) __half2 smh[];

    const int tid  = threadIdx.x;
    const int wid  = tid >> 5;
    const int lane = tid & 31;
    const int grp  = lane >> 2;
    const int thr4 = lane & 3;

    const int zq = blockIdx.x;
    const int xq = blockIdx.y & 3;
    const int ch = blockIdx.y >> 2;
    const int b  = blockIdx.z;
    const int cta = (blockIdx.z * 8 + blockIdx.y) * 32 + blockIdx.x;

    const int n0 = (wid >> 2) * 32;    // warp N offset
    const int zl = wid & 3;            // z row within CTA tile (uniform per warp)

    const uint32_t smu = (uint32_t)__cvta_generic_to_shared(smh);
    float* sc = g_S + (size_t)cta * 32768;   // dv-major tile [dv][z4][x32][c64]

    // stage s: dv = s>>1, ck = s&1, buffer = s&1
#define STAGE_FILL(s_)                                                          \
    {                                                                           \
        const int dv_ = (s_) >> 1, ck_ = (s_) & 1;                              \
        const uint32_t base = smu + ((s_) & 1) * (BUF_H * 2);                   \
        const __half* p1b = g_P1h + ((size_t)((b * NDV + dv_) * NZ + zq * 4)) * NR + ck_ * KC;  \
        const __half* p2b = g_P2h + ((size_t)((b * NDV + dv_) * NZ + xq * 32)) * NR + ck_ * KC; \
        const __half* p3b = g_P3h + ((size_t)((b * NDV + dv_) * NZ + ch * 64)) * NR + ck_ * KC; \
        if (tid < 64) {                                                         \
            int r = tid >> 4, q = tid & 15;                                     \
            cp16(base + (r * HPAD + q * 8) * 2, p1b + r * NR + q * 8);          \
        }                                                                       \
        _Pragma("unroll")                                                       \
        for (int i = 0; i < 2; i++) {                                           \
            int g = i * 256 + tid, r = g >> 4, q = g & 15;                      \
            cp16(base + (OFF_P2H + r * HPAD + q * 8) * 2, p2b + r * NR + q * 8);\
        }                                                                       \
        _Pragma("unroll")                                                       \
        for (int i = 0; i < 4; i++) {                                           \
            int g = i * 256 + tid, r = g >> 4, q = g & 15;                      \
            cp16(base + (OFF_P3H + r * HPAD + q * 8) * 2, p3b + r * NR + q * 8);\
        }                                                                       \
    }

    float d[2][4][4];

    STAGE_FILL(0);
    cp_commit();

    for (int s = 0; s < 8; s++) {
        const int dv = s >> 1, ck = s & 1;
        if (s + 1 < 8) {
            STAGE_FILL(s + 1);
            cp_commit();
            cp_wait<1>();
        } else {
            cp_wait<0>();
        }
        __syncthreads();

        if (ck == 0) {
#pragma unroll
            for (int t = 0; t < 2; t++)
#pragma unroll
                for (int j = 0; j < 4; j++)
#pragma unroll
                    for (int i = 0; i < 4; i++) d[t][j][i] = 0.0f;
        }

        const __half2* p1s = smh + (s & 1) * BUF_H / 2;
        const __half2* p2s = p1s + OFF_P2H / 2;
        const __half2* p3s = p1s + OFF_P3H / 2;

#pragma unroll
        for (int kk = 0; kk < KC / 16; kk++) {
            const int fo = kk * 8 + 2 * thr4;   // half2 idx of this thread's frag

            // One LDS.64 per fragment: .x = k{2t,2t+1}, .y = k{2t+8,2t+9}
            uint2 p1p = *(const uint2*)&p1s[zl * 68 + fo];

            uint32_t a[2][4];
#pragma unroll
            for (int t = 0; t < 2; t++) {
                const int x0 = 16 * t + grp;
                uint2 v0 = *(const uint2*)&p2s[x0 * 68 + fo];
                uint2 v1 = *(const uint2*)&p2s[(x0 + 8) * 68 + fo];
                a[t][0] = hmul2r(p1p.x, v0.x);
                a[t][1] = hmul2r(p1p.x, v1.x);
                a[t][2] = hmul2r(p1p.y, v0.y);
                a[t][3] = hmul2r(p1p.y, v1.y);
            }
#pragma unroll
            for (int j = 0; j < 4; j++) {
                const int c = n0 + j * 8 + grp;
                uint2 bp = *(const uint2*)&p3s[c * 68 + fo];
#pragma unroll
                for (int t = 0; t < 2; t++)
                    asm volatile(
                        "mma.sync.aligned.m16n8k16.row.col.f32.f16.f16.f32 "
                        "{%0,%1,%2,%3}, {%4,%5,%6,%7}, {%8,%9}, {%0,%1,%2,%3};"
                        : "+f"(d[t][j][0]), "+f"(d[t][j][1]),
                          "+f"(d[t][j][2]), "+f"(d[t][j][3])
                        : "r"(a[t][0]), "r"(a[t][1]), "r"(a[t][2]), "r"(a[t][3]),
                          "r"(bp.x), "r"(bp.y));
            }
        }

        if (ck == 1) {
            // Park this dv's tile in the dv-major scratch (dense, L1-bypass).
#pragma unroll
            for (int t = 0; t < 2; t++) {
                const int xa = 16 * t + grp;
#pragma unroll
                for (int j = 0; j < 4; j++) {
                    const int cgl = n0 + j * 8 + thr4 * 2;
                    int i0 = dv * 8192 + zl * 2048 + xa * 64 + cgl;
                    stg_cg_v2(&sc[i0],          d[t][j][0], d[t][j][1]);
                    stg_cg_v2(&sc[i0 + 8 * 64], d[t][j][2], d[t][j][3]);
                }
            }
        }
        __syncthreads();
    }
#undef STAGE_FILL

    // Fused tail: re-read the (L2-hot) scratch tile and write out[] as dense
    // float4 (all 4 dv per store). 8192 positions, 32 per thread, coalesced.
    float4* o4 = (float4*)out;
#pragma unroll
    for (int i = 0; i < 32; i++) {
        int f   = i * 256 + tid;       // 0..8191
        int c   = f & 63;
        int xa  = (f >> 6) & 31;
        int zz  = f >> 11;             // 0..3
        int p   = zz * 2048 + xa * 64 + c;
        float4 v;
        v.x = sc[p];
        v.y = sc[p + 8192];
        v.z = sc[p + 16384];
        v.w = sc[p + 24576];
        size_t oi = (((size_t)(b * NZ + zq * 4 + zz) * NZ + xq * 32 + xa) * NZ
                     + ch * 64 + c);
        o4[oi] = v;
    }
}

// ---------------------------------------------------------------------------
extern "C" void kernel_launch(void* const* d_in, const int* in_sizes, int n_in,
                              void* d_out, int out_size)
{
    (void)in_sizes; (void)n_in; (void)out_size;
    const float* x1 = (const float*)d_in[0];
    const float* x2 = (const float*)d_in[1];
    const float* x3 = (const float*)d_in[2];
    const float* W1 = (const float*)d_in[3];
    const float* b1 = (const float*)d_in[4];
    const float* W2 = (const float*)d_in[5];
    const float* b2 = (const float*)d_in[6];
    const float* W3 = (const float*)d_in[7];
    const float* b3 = (const float*)d_in[8];
    float* out = (float*)d_out;

    static int attr_done = 0;
    if (!attr_done) {
        cudaFuncSetAttribute(tri_mma_kernel,
                             cudaFuncAttributeMaxDynamicSharedMemorySize, SMEM_BYTES);
        cudaFuncSetAttribute(proj_kernel,
                             cudaFuncAttributeMaxDynamicSharedMemorySize, PROJ_SMEM);
        attr_done = 1;
    }

    proj_kernel<<<dim3(NZ / ZG, NB, 3), 256, PROJ_SMEM>>>(x1, x2, x3, W1, b1, W2, b2, W3, b3);
    tri_mma_kernel<<<dim3(32, 8, NB), 256, SMEM_BYTES>>>(out);
}

// round 16
// speedup vs baseline: 1.2019x; 1.2019x over previous
#include <cuda_runtime.h>
#include <cuda_fp16.h>
#include <cstdint>

// FactorizedTrilinear: B=4, Z=X=C=128, D=V=2 (dv=4), IN=512, R=256
// proj: P_k[b][dv][row][e] = fp16( x_k[b,row,dv,:] @ W_k + b_k )
// tri:  out[b,z,x,c,dv] = sum_e (p1*p2)*p3 via mma.sync.m16n8k16.f16,
//       CTA M128(4z x 32x) x N64(c), KC=128 fp16 double-buffer, 3 CTAs/SM,
//       ldmatrix.x4 fragment loads, dv-major global scratch + dense tail.

#define NB  4
#define NZ  128
#define NIN 512
#define NR  256
#define NDV 4

__device__ __align__(16) __half g_P1h[NB * NDV * NZ * NR];
__device__ __align__(16) __half g_P2h[NB * NDV * NZ * NR];
__device__ __align__(16) __half g_P3h[NB * NDV * NZ * NR];
// Per-CTA scratch tiles: 1024 CTAs x 32768 floats (dv-major) = 128 MB.
__device__ __align__(16) float  g_S[1024 * 32768];

__device__ __forceinline__ void cp16(uint32_t dst, const void* src) {
    asm volatile("cp.async.cg.shared.global [%0], [%1], 16;"
                 :: "r"(dst), "l"(src) : "memory");
}
__device__ __forceinline__ void cp_commit() {
    asm volatile("cp.async.commit_group;" ::: "memory");
}
template <int N>
__device__ __forceinline__ void cp_wait() {
    asm volatile("cp.async.wait_group %0;" :: "n"(N) : "memory");
}
__device__ __forceinline__ uint32_t hmul2u(__half2 a, __half2 b) {
    __half2 r = __hmul2(a, b);
    return *(uint32_t*)&r;
}
#define LDSM4(R, A)                                                          \
    asm volatile("ldmatrix.sync.aligned.m8n8.x4.shared.b16 "                 \
                 "{%0,%1,%2,%3}, [%4];"                                      \
                 : "=r"((R)[0]), "=r"((R)[1]), "=r"((R)[2]), "=r"((R)[3])    \
                 : "r"(A))

// ---------------------------------------------------------------------------
// Projection (exact R12): grid (32, 4, 3), 256 threads, 64 KB dynamic smem.
// Block = 4 z rows, r = tid. W streamed in 16-e chunks, cp.async double-buffered.
// All P stored fp16, natural e order.
// ---------------------------------------------------------------------------
#define PROJ_SMEM ((4 * NIN * NDV + 2 * 16 * NR) * 4)   // 32KB + 32KB

__global__ __launch_bounds__(256) void proj_kernel(
    const float* __restrict__ x1, const float* __restrict__ x2, const float* __restrict__ x3,
    const float* __restrict__ W1, const float* __restrict__ bb1,
    const float* __restrict__ W2, const float* __restrict__ bb2,
    const float* __restrict__ W3, const float* __restrict__ bb3)
{
    extern __shared__ __align__(16) float psm[];
    float* xs = psm;                      // [z][e][dv] 4*512*4 floats
    float* ws = psm + 4 * NIN * NDV;      // 2 x [e16][r] 16*256 floats each

    const int z0 = blockIdx.x * 4;
    const int b  = blockIdx.y;
    const int k  = blockIdx.z;

    const float* x  = (k == 0) ? x1  : (k == 1) ? x2  : x3;
    const float* W  = (k == 0) ? W1  : (k == 1) ? W2  : W3;
    const float* bs = (k == 0) ? bb1 : (k == 1) ? bb2 : bb3;
    __half*      P  = (k == 0) ? g_P1h : (k == 1) ? g_P2h : g_P3h;

    const int tid = threadIdx.x;
    const uint32_t wsu = (uint32_t)__cvta_generic_to_shared(ws);

    const float* xg = x + ((size_t)(b * NZ + z0)) * NDV * NIN;
#pragma unroll
    for (int i = 0; i < 32; i++) {
        int idx = i * 256 + tid;
        int e   = idx & (NIN - 1);
        int zdv = idx >> 9;
        xs[((zdv >> 2) * NIN + e) * NDV + (zdv & 3)] = xg[zdv * NIN + e];
    }

#define WFILL(ec_)                                                      \
    {                                                                   \
        const float4* wg = (const float4*)(W + (ec_) * 16 * NR);        \
        uint32_t base = wsu + ((ec_) & 1) * (16 * NR * 4);              \
        _Pragma("unroll")                                               \
        for (int i = 0; i < 4; i++)                                     \
            cp16(base + (i * 256 + tid) * 16, wg + i * 256 + tid);      \
    }

    float acc[4][NDV];
    {
        float bv = bs[tid];
#pragma unroll
        for (int z = 0; z < 4; z++)
#pragma unroll
            for (int dv = 0; dv < NDV; dv++) acc[z][dv] = bv;
    }

    WFILL(0);
    cp_commit();

    for (int ec = 0; ec < NIN / 16; ec++) {
        if (ec + 1 < NIN / 16) {
            WFILL(ec + 1);
            cp_commit();
            cp_wait<1>();
        } else {
            cp_wait<0>();
        }
        __syncthreads();

        const float* w = ws + (ec & 1) * 16 * NR;
#pragma unroll
        for (int e16 = 0; e16 < 16; e16++) {
            float wv = w[e16 * NR + tid];
            int e = ec * 16 + e16;
#pragma unroll
            for (int z = 0; z < 4; z++) {
                float4 xv = *(const float4*)&xs[(z * NIN + e) * NDV];
                acc[z][0] = fmaf(xv.x, wv, acc[z][0]);
                acc[z][1] = fmaf(xv.y, wv, acc[z][1]);
                acc[z][2] = fmaf(xv.z, wv, acc[z][2]);
                acc[z][3] = fmaf(xv.w, wv, acc[z][3]);
            }
        }
        __syncthreads();
    }
#undef WFILL

#pragma unroll
    for (int z = 0; z < 4; z++)
#pragma unroll
        for (int dv = 0; dv < NDV; dv++)
            P[((size_t)((b * NDV + dv) * NZ + z0 + z)) * NR + tid] =
                __float2half_rn(acc[z][dv]);
}

// ---------------------------------------------------------------------------
// Trilinear. Grid (32, 8, 4): zq x [xq|ch] x b. CTA: M=128(4z x 32x), N=64(c).
// 8 warps = 4M x 2N; warp tile M32 x N32 (2 m-tiles x 4 n-tiles m16n8k16 f16).
// dv(4) x ck(2 x KC=128), fp16 staging double-buffered (54.4 KB, 3 CTAs/SM).
// p2 (A-layout) and p3 (B-layout) fragments via ldmatrix.m8n8.x4.
// ---------------------------------------------------------------------------
#define KC    128
#define HPAD  136                         // halves per row (h2 stride 68)
#define OFF_P2H  (4 * HPAD)               // 544 halves
#define OFF_P3H  (OFF_P2H + 32 * HPAD)    // 4896 halves
#define BUF_H    (OFF_P3H + 64 * HPAD)    // 13600 halves = 27200 B
#define SMEM_BYTES (2 * BUF_H * 2)        // 54400

__global__ __launch_bounds__(256, 3) void tri_mma_kernel(float* __restrict__ out)
{
    extern __shared__ __align__(16) __half2 smh[];

    const int tid  = threadIdx.x;
    const int wid  = tid >> 5;
    const int lane = tid & 31;
    const int grp  = lane >> 2;
    const int thr4 = lane & 3;

    const int zq = blockIdx.x;
    const int xq = blockIdx.y & 3;
    const int ch = blockIdx.y >> 2;
    const int b  = blockIdx.z;
    const int cta = (blockIdx.z * 8 + blockIdx.y) * 32 + blockIdx.x;

    const int n0 = (wid >> 2) * 32;    // warp N offset
    const int zl = wid & 3;            // z row within CTA tile (uniform per warp)

    const uint32_t smu = (uint32_t)__cvta_generic_to_shared(smh);
    float* sc = g_S + (size_t)cta * 32768;   // dv-major tile [dv][z4][x32][c64]

    // ldmatrix per-lane address components (byte offsets within a buffer).
    // p2 (A-frag, t-tile): mats = [rows+0 klo, rows+8 klo, rows+0 khi, rows+8 khi]
    //   row = 16t + (mat&1)*8 + r8, kOff = (mat>>1)*8 halves
    // p3 (B-frag, n-tile pair jp): mats = [n+0 klo, n+0 khi, n+8 klo, n+8 khi]
    //   row = n0 + jp*16 + (mat>>1)*8 + r8, kOff = (mat&1)*8 halves
    const int r8  = lane & 7;
    const int mat = lane >> 3;
    uint32_t p2off[2], p3off[2];
#pragma unroll
    for (int t = 0; t < 2; t++)
        p2off[t] = (OFF_P2H +
                    (uint32_t)((16 * t + ((mat & 1) << 3) + r8) * HPAD +
                               ((mat >> 1) << 3))) * 2;
#pragma unroll
    for (int jp = 0; jp < 2; jp++)
        p3off[jp] = (OFF_P3H +
                     (uint32_t)((n0 + jp * 16 + ((mat >> 1) << 3) + r8) * HPAD +
                                ((mat & 1) << 3))) * 2;

    // stage s: dv = s>>1, ck = s&1, buffer = s&1
#define STAGE_FILL(s_)                                                          \
    {                                                                           \
        const int dv_ = (s_) >> 1, ck_ = (s_) & 1;                              \
        const uint32_t base = smu + ((s_) & 1) * (BUF_H * 2);                   \
        const __half* p1b = g_P1h + ((size_t)((b * NDV + dv_) * NZ + zq * 4)) * NR + ck_ * KC;  \
        const __half* p2b = g_P2h + ((size_t)((b * NDV + dv_) * NZ + xq * 32)) * NR + ck_ * KC; \
        const __half* p3b = g_P3h + ((size_t)((b * NDV + dv_) * NZ + ch * 64)) * NR + ck_ * KC; \
        if (tid < 64) {                                                         \
            int r = tid >> 4, q = tid & 15;                                     \
            cp16(base + (r * HPAD + q * 8) * 2, p1b + r * NR + q * 8);          \
        }                                                                       \
        _Pragma("unroll")                                                       \
        for (int i = 0; i < 2; i++) {                                           \
            int g = i * 256 + tid, r = g >> 4, q = g & 15;                      \
            cp16(base + (OFF_P2H + r * HPAD + q * 8) * 2, p2b + r * NR + q * 8);\
        }                                                                       \
        _Pragma("unroll")                                                       \
        for (int i = 0; i < 4; i++) {                                           \
            int g = i * 256 + tid, r = g >> 4, q = g & 15;                      \
            cp16(base + (OFF_P3H + r * HPAD + q * 8) * 2, p3b + r * NR + q * 8);\
        }                                                                       \
    }

    float d[2][4][4];

    STAGE_FILL(0);
    cp_commit();

    for (int s = 0; s < 8; s++) {
        const int dv = s >> 1, ck = s & 1;
        if (s + 1 < 8) {
            STAGE_FILL(s + 1);
            cp_commit();
            cp_wait<1>();
        } else {
            cp_wait<0>();
        }
        __syncthreads();

        if (ck == 0) {
#pragma unroll
            for (int t = 0; t < 2; t++)
#pragma unroll
                for (int j = 0; j < 4; j++)
#pragma unroll
                    for (int i = 0; i < 4; i++) d[t][j][i] = 0.0f;
        }

        const uint32_t bufb = smu + (s & 1) * (BUF_H * 2);
        const __half2* p1s = smh + (s & 1) * BUF_H / 2;
        const uint32_t pa2_0 = bufb + p2off[0];
        const uint32_t pa2_1 = bufb + p2off[1];
        const uint32_t pa3_0 = bufb + p3off[0];
        const uint32_t pa3_1 = bufb + p3off[1];

#pragma unroll
        for (int kk = 0; kk < KC / 16; kk++) {
            const int k2lo = kk * 8 + thr4;   // half2 index of k = kk*16+2*thr4
            const int k2hi = k2lo + 4;

            __half2 p1lo = p1s[zl * 68 + k2lo];
            __half2 p1hi = p1s[zl * 68 + k2hi];

            uint32_t f0[4], f1[4], bq[4], br[4];
            LDSM4(f0, pa2_0 + kk * 32);   // t=0: a-layout frags of p2
            LDSM4(f1, pa2_1 + kk * 32);   // t=1
            LDSM4(bq, pa3_0 + kk * 32);   // j0: {b0,b1}, j1: {b0,b1}
            LDSM4(br, pa3_1 + kk * 32);   // j2, j3

            uint32_t a[2][4];
#pragma unroll
            for (int t = 0; t < 2; t++) {
                const uint32_t* f = t ? f1 : f0;
                a[t][0] = hmul2u(p1lo, *(__half2*)&f[0]);
                a[t][1] = hmul2u(p1lo, *(__half2*)&f[1]);
                a[t][2] = hmul2u(p1hi, *(__half2*)&f[2]);
                a[t][3] = hmul2u(p1hi, *(__half2*)&f[3]);
            }
#pragma unroll
            for (int j = 0; j < 4; j++) {
                const uint32_t b0 = (j < 2) ? bq[2 * j]     : br[2 * (j - 2)];
                const uint32_t b1 = (j < 2) ? bq[2 * j + 1] : br[2 * (j - 2) + 1];
#pragma unroll
                for (int t = 0; t < 2; t++)
                    asm volatile(
                        "mma.sync.aligned.m16n8k16.row.col.f32.f16.f16.f32 "
                        "{%0,%1,%2,%3}, {%4,%5,%6,%7}, {%8,%9}, {%0,%1,%2,%3};"
                        : "+f"(d[t][j][0]), "+f"(d[t][j][1]),
                          "+f"(d[t][j][2]), "+f"(d[t][j][3])
                        : "r"(a[t][0]), "r"(a[t][1]), "r"(a[t][2]), "r"(a[t][3]),
                          "r"(b0), "r"(b1));
            }
        }

        if (ck == 1) {
            // Park this dv's tile in the dv-major scratch (dense float2 stores).
#pragma unroll
            for (int t = 0; t < 2; t++) {
                const int xa = 16 * t + grp;
#pragma unroll
                for (int j = 0; j < 4; j++) {
                    const int cgl = n0 + j * 8 + thr4 * 2;
                    int i0 = dv * 8192 + zl * 2048 + xa * 64 + cgl;
                    *(float2*)&sc[i0]          = make_float2(d[t][j][0], d[t][j][1]);
                    *(float2*)&sc[i0 + 8 * 64] = make_float2(d[t][j][2], d[t][j][3]);
                }
            }
        }
        __syncthreads();
    }
#undef STAGE_FILL

    // Fused tail: re-read the (L2-hot) scratch tile and write out[] as dense
    // float4 (all 4 dv per store). 8192 positions, 32 per thread, coalesced.
    float4* o4 = (float4*)out;
#pragma unroll
    for (int i = 0; i < 32; i++) {
        int f   = i * 256 + tid;       // 0..8191
        int c   = f & 63;
        int xa  = (f >> 6) & 31;
        int zz  = f >> 11;             // 0..3
        int p   = zz * 2048 + xa * 64 + c;
        float4 v;
        v.x = sc[p];
        v.y = sc[p + 8192];
        v.z = sc[p + 16384];
        v.w = sc[p + 24576];
        size_t oi = (((size_t)(b * NZ + zq * 4 + zz) * NZ + xq * 32 + xa) * NZ
                     + ch * 64 + c);
        o4[oi] = v;
    }
}

// ---------------------------------------------------------------------------
extern "C" void kernel_launch(void* const* d_in, const int* in_sizes, int n_in,
                              void* d_out, int out_size)
{
    (void)in_sizes; (void)n_in; (void)out_size;
    const float* x1 = (const float*)d_in[0];
    const float* x2 = (const float*)d_in[1];
    const float* x3 = (const float*)d_in[2];
    const float* W1 = (const float*)d_in[3];
    const float* b1 = (const float*)d_in[4];
    const float* W2 = (const float*)d_in[5];
    const float* b2 = (const float*)d_in[6];
    const float* W3 = (const float*)d_in[7];
    const float* b3 = (const float*)d_in[8];
    float* out = (float*)d_out;

    static int attr_done = 0;
    if (!attr_done) {
        cudaFuncSetAttribute(tri_mma_kernel,
                             cudaFuncAttributeMaxDynamicSharedMemorySize, SMEM_BYTES);
        cudaFuncSetAttribute(proj_kernel,
                             cudaFuncAttributeMaxDynamicSharedMemorySize, PROJ_SMEM);
        attr_done = 1;
    }

    proj_kernel<<<dim3(32, NB, 3), 256, PROJ_SMEM>>>(x1, x2, x3, W1, b1, W2, b2, W3, b3);
    tri_mma_kernel<<<dim3(32, 8, NB), 256, SMEM_BYTES>>>(out);
}

// round 17
// speedup vs baseline: 1.6564x; 1.3781x over previous
#include <cuda_runtime.h>
#include <cuda_fp16.h>
#include <cstdint>

// FactorizedTrilinear: B=4, Z=X=C=128, D=V=2 (dv=4), IN=512, R=256
// proj (tf32 mma): P_k[b][dv][z][r] = fp16( x_k row . W_k col + b_k[r] )
//   CTA M64(16z x 4dv) x N128(r) x K512 (8 chunks of 64, cp.async dbl-buffer)
// tri (exact R16): out[b,z,x,c,dv] = sum_e (p1*p2)*p3 via mma.m16n8k16.f16,
//   ldmatrix.x4 frags, dv-major global scratch + dense float4 tail.

#define NB  4
#define NZ  128
#define NIN 512
#define NR  256
#define NDV 4

__device__ __align__(16) __half g_P1h[NB * NDV * NZ * NR];
__device__ __align__(16) __half g_P2h[NB * NDV * NZ * NR];
__device__ __align__(16) __half g_P3h[NB * NDV * NZ * NR];
// Per-CTA scratch tiles: 1024 CTAs x 32768 floats (dv-major) = 128 MB.
__device__ __align__(16) float  g_S[1024 * 32768];

__device__ __forceinline__ void cp16(uint32_t dst, const void* src) {
    asm volatile("cp.async.cg.shared.global [%0], [%1], 16;"
                 :: "r"(dst), "l"(src) : "memory");
}
__device__ __forceinline__ void cp_commit() {
    asm volatile("cp.async.commit_group;" ::: "memory");
}
template <int N>
__device__ __forceinline__ void cp_wait() {
    asm volatile("cp.async.wait_group %0;" :: "n"(N) : "memory");
}
__device__ __forceinline__ uint32_t f2tf32(float f) {
    uint32_t u;
    asm("cvt.rna.tf32.f32 %0, %1;" : "=r"(u) : "f"(f));
    return u;
}
__device__ __forceinline__ uint32_t hmul2u(__half2 a, __half2 b) {
    __half2 r = __hmul2(a, b);
    return *(uint32_t*)&r;
}
#define LDSM4(R, A)                                                          \
    asm volatile("ldmatrix.sync.aligned.m8n8.x4.shared.b16 "                 \
                 "{%0,%1,%2,%3}, [%4];"                                      \
                 : "=r"((R)[0]), "=r"((R)[1]), "=r"((R)[2]), "=r"((R)[3])    \
                 : "r"(A))

// ---------------------------------------------------------------------------
// Projection via tf32 MMA. Grid (16, 4, 3): bx = mt*2+nt, b, k. 256 threads.
// CTA: M64 rows (x rows m = z*4+dv, contiguous) x N128 r x K512.
// 8 warps = 2M x 4N; warp tile M32 x N32 (2 m-tiles x 4 n-tiles m16n8k8).
// smem: xs[64][68] fp32 + ws[64][136] fp32, double-buffered (102 KB).
// ---------------------------------------------------------------------------
#define XS_F   (64 * 68)                 // 4352 floats
#define WS_F   (64 * 136)                // 8704 floats
#define BUFP_F (XS_F + WS_F)             // 13056 floats
#define XS_B   (XS_F * 4)                // 17408 bytes
#define PROJ_SMEM (2 * BUFP_F * 4)       // 104448 bytes

__global__ __launch_bounds__(256, 2) void proj_mma_kernel(
    const float* __restrict__ x1, const float* __restrict__ x2, const float* __restrict__ x3,
    const float* __restrict__ W1, const float* __restrict__ bb1,
    const float* __restrict__ W2, const float* __restrict__ bb2,
    const float* __restrict__ W3, const float* __restrict__ bb3)
{
    extern __shared__ __align__(16) float psm[];

    const int tid  = threadIdx.x;
    const int wid  = tid >> 5;
    const int lane = tid & 31;
    const int grp  = lane >> 2;
    const int thr4 = lane & 3;

    const int mt = blockIdx.x >> 1;      // 0..7  (64-row tile within b's 512)
    const int nt = blockIdx.x & 1;       // 0..1  (128-col tile of r)
    const int b  = blockIdx.y;
    const int k  = blockIdx.z;

    const float* x  = (k == 0) ? x1  : (k == 1) ? x2  : x3;
    const float* W  = (k == 0) ? W1  : (k == 1) ? W2  : W3;
    const float* bs = (k == 0) ? bb1 : (k == 1) ? bb2 : bb3;
    __half*      P  = (k == 0) ? g_P1h : (k == 1) ? g_P2h : g_P3h;

    const int wm = (wid & 1) * 32;       // warp M offset (2 M warps)
    const int wn = (wid >> 1) * 32;      // warp N offset (4 N warps)

    const float* xg = x + ((size_t)(b * 512 + mt * 64)) * NIN;   // [64][512]
    const float* wg = W + nt * 128;                              // [512][256] col slice
    const uint32_t psu = (uint32_t)__cvta_generic_to_shared(psm);

    // Bias (uniform over tt/rr; depends on j,thr4).
    float2 bias[4];
#pragma unroll
    for (int j = 0; j < 4; j++) {
        int r = nt * 128 + wn + j * 8 + 2 * thr4;
        bias[j] = make_float2(bs[r], bs[r + 1]);
    }

#define PSTAGE(c_)                                                            \
    {                                                                         \
        const int k0_ = (c_) * 64;                                            \
        const uint32_t base = psu + ((c_) & 1) * (BUFP_F * 4);                \
        _Pragma("unroll")                                                     \
        for (int i = 0; i < 4; i++) {                                         \
            int f = i * 256 + tid, row = f >> 4, q = f & 15;                  \
            cp16(base + (row * 68 + q * 4) * 4,                               \
                 xg + (size_t)row * NIN + k0_ + q * 4);                       \
        }                                                                     \
        _Pragma("unroll")                                                     \
        for (int i = 0; i < 8; i++) {                                         \
            int f = i * 256 + tid, e = f >> 5, q = f & 31;                    \
            cp16(base + XS_B + (e * 136 + q * 4) * 4,                         \
                 wg + (size_t)(k0_ + e) * NR + q * 4);                        \
        }                                                                     \
    }

    float d[2][4][4];
#pragma unroll
    for (int tt = 0; tt < 2; tt++)
#pragma unroll
        for (int j = 0; j < 4; j++)
#pragma unroll
            for (int i = 0; i < 4; i++) d[tt][j][i] = 0.0f;

    PSTAGE(0);
    cp_commit();

    for (int c = 0; c < 8; c++) {
        if (c + 1 < 8) {
            PSTAGE(c + 1);
            cp_commit();
            cp_wait<1>();
        } else {
            cp_wait<0>();
        }
        __syncthreads();

        const float* xsp = psm + (c & 1) * BUFP_F;   // [row][68]
        const float* wsp = xsp + XS_F;               // [e][136]

#pragma unroll
        for (int kk = 0; kk < 8; kk++) {
            const int kq = kk * 8 + thr4;

            uint32_t a[2][4];
#pragma unroll
            for (int tt = 0; tt < 2; tt++) {
                const int r0 = wm + 16 * tt + grp;
                a[tt][0] = f2tf32(xsp[r0 * 68 + kq]);
                a[tt][1] = f2tf32(xsp[(r0 + 8) * 68 + kq]);
                a[tt][2] = f2tf32(xsp[r0 * 68 + kq + 4]);
                a[tt][3] = f2tf32(xsp[(r0 + 8) * 68 + kq + 4]);
            }
#pragma unroll
            for (int j = 0; j < 4; j++) {
                const int n = wn + j * 8 + grp;
                uint32_t b0 = f2tf32(wsp[kq * 136 + n]);
                uint32_t b1 = f2tf32(wsp[(kq + 4) * 136 + n]);
#pragma unroll
                for (int tt = 0; tt < 2; tt++)
                    asm volatile(
                        "mma.sync.aligned.m16n8k8.row.col.f32.tf32.tf32.f32 "
                        "{%0,%1,%2,%3}, {%4,%5,%6,%7}, {%8,%9}, {%0,%1,%2,%3};"
                        : "+f"(d[tt][j][0]), "+f"(d[tt][j][1]),
                          "+f"(d[tt][j][2]), "+f"(d[tt][j][3])
                        : "r"(a[tt][0]), "r"(a[tt][1]), "r"(a[tt][2]), "r"(a[tt][3]),
                          "r"(b0), "r"(b1));
            }
        }
        __syncthreads();
    }
#undef PSTAGE

    // Epilogue: add bias, round to fp16, store to P[b][dv][z][r] (r even pairs).
    uint32_t* Ph = (uint32_t*)P;
#pragma unroll
    for (int tt = 0; tt < 2; tt++) {
#pragma unroll
        for (int rr = 0; rr < 2; rr++) {
            const int mrow = mt * 64 + wm + 16 * tt + grp + 8 * rr;
            const int z  = mrow >> 2;
            const int dv = mrow & 3;
            const size_t rowbase = ((size_t)((b * NDV + dv) * NZ + z)) * NR;
#pragma unroll
            for (int j = 0; j < 4; j++) {
                const int r = nt * 128 + wn + j * 8 + 2 * thr4;
                __half2 h = __floats2half2_rn(d[tt][j][2 * rr]     + bias[j].x,
                                              d[tt][j][2 * rr + 1] + bias[j].y);
                Ph[(rowbase + r) >> 1] = *(uint32_t*)&h;
            }
        }
    }
}

// ---------------------------------------------------------------------------
// Trilinear (exact R16). Grid (32, 8, 4). CTA M128(4z x 32x) x N64(c).
// ---------------------------------------------------------------------------
#define KC    128
#define HPAD  136
#define OFF_P2H  (4 * HPAD)
#define OFF_P3H  (OFF_P2H + 32 * HPAD)
#define BUF_H    (OFF_P3H + 64 * HPAD)
#define SMEM_BYTES (2 * BUF_H * 2)

__global__ __launch_bounds__(256, 3) void tri_mma_kernel(float* __restrict__ out)
{
    extern __shared__ __align__(16) __half2 smh[];

    const int tid  = threadIdx.x;
    const int wid  = tid >> 5;
    const int lane = tid & 31;
    const int grp  = lane >> 2;
    const int thr4 = lane & 3;

    const int zq = blockIdx.x;
    const int xq = blockIdx.y & 3;
    const int ch = blockIdx.y >> 2;
    const int b  = blockIdx.z;
    const int cta = (blockIdx.z * 8 + blockIdx.y) * 32 + blockIdx.x;

    const int n0 = (wid >> 2) * 32;
    const int zl = wid & 3;

    const uint32_t smu = (uint32_t)__cvta_generic_to_shared(smh);
    float* sc = g_S + (size_t)cta * 32768;

    const int r8  = lane & 7;
    const int mat = lane >> 3;
    uint32_t p2off[2], p3off[2];
#pragma unroll
    for (int t = 0; t < 2; t++)
        p2off[t] = (OFF_P2H +
                    (uint32_t)((16 * t + ((mat & 1) << 3) + r8) * HPAD +
                               ((mat >> 1) << 3))) * 2;
#pragma unroll
    for (int jp = 0; jp < 2; jp++)
        p3off[jp] = (OFF_P3H +
                     (uint32_t)((n0 + jp * 16 + ((mat >> 1) << 3) + r8) * HPAD +
                                ((mat & 1) << 3))) * 2;

#define STAGE_FILL(s_)                                                          \
    {                                                                           \
        const int dv_ = (s_) >> 1, ck_ = (s_) & 1;                              \
        const uint32_t base = smu + ((s_) & 1) * (BUF_H * 2);                   \
        const __half* p1b = g_P1h + ((size_t)((b * NDV + dv_) * NZ + zq * 4)) * NR + ck_ * KC;  \
        const __half* p2b = g_P2h + ((size_t)((b * NDV + dv_) * NZ + xq * 32)) * NR + ck_ * KC; \
        const __half* p3b = g_P3h + ((size_t)((b * NDV + dv_) * NZ + ch * 64)) * NR + ck_ * KC; \
        if (tid < 64) {                                                         \
            int r = tid >> 4, q = tid & 15;                                     \
            cp16(base + (r * HPAD + q * 8) * 2, p1b + r * NR + q * 8);          \
        }                                                                       \
        _Pragma("unroll")                                                       \
        for (int i = 0; i < 2; i++) {                                           \
            int g = i * 256 + tid, r = g >> 4, q = g & 15;                      \
            cp16(base + (OFF_P2H + r * HPAD + q * 8) * 2, p2b + r * NR + q * 8);\
        }                                                                       \
        _Pragma("unroll")                                                       \
        for (int i = 0; i < 4; i++) {                                           \
            int g = i * 256 + tid, r = g >> 4, q = g & 15;                      \
            cp16(base + (OFF_P3H + r * HPAD + q * 8) * 2, p3b + r * NR + q * 8);\
        }                                                                       \
    }

    float d[2][4][4];

    STAGE_FILL(0);
    cp_commit();

    for (int s = 0; s < 8; s++) {
        const int dv = s >> 1, ck = s & 1;
        if (s + 1 < 8) {
            STAGE_FILL(s + 1);
            cp_commit();
            cp_wait<1>();
        } else {
            cp_wait<0>();
        }
        __syncthreads();

        if (ck == 0) {
#pragma unroll
            for (int t = 0; t < 2; t++)
#pragma unroll
                for (int j = 0; j < 4; j++)
#pragma unroll
                    for (int i = 0; i < 4; i++) d[t][j][i] = 0.0f;
        }

        const uint32_t bufb = smu + (s & 1) * (BUF_H * 2);
        const __half2* p1s = smh + (s & 1) * BUF_H / 2;
        const uint32_t pa2_0 = bufb + p2off[0];
        const uint32_t pa2_1 = bufb + p2off[1];
        const uint32_t pa3_0 = bufb + p3off[0];
        const uint32_t pa3_1 = bufb + p3off[1];

#pragma unroll
        for (int kk = 0; kk < KC / 16; kk++) {
            const int k2lo = kk * 8 + thr4;
            const int k2hi = k2lo + 4;

            __half2 p1lo = p1s[zl * 68 + k2lo];
            __half2 p1hi = p1s[zl * 68 + k2hi];

            uint32_t f0[4], f1[4], bq[4], br[4];
            LDSM4(f0, pa2_0 + kk * 32);
            LDSM4(f1, pa2_1 + kk * 32);
            LDSM4(bq, pa3_0 + kk * 32);
            LDSM4(br, pa3_1 + kk * 32);

            uint32_t a[2][4];
#pragma unroll
            for (int t = 0; t < 2; t++) {
                const uint32_t* f = t ? f1 : f0;
                a[t][0] = hmul2u(p1lo, *(__half2*)&f[0]);
                a[t][1] = hmul2u(p1lo, *(__half2*)&f[1]);
                a[t][2] = hmul2u(p1hi, *(__half2*)&f[2]);
                a[t][3] = hmul2u(p1hi, *(__half2*)&f[3]);
            }
#pragma unroll
            for (int j = 0; j < 4; j++) {
                const uint32_t b0 = (j < 2) ? bq[2 * j]     : br[2 * (j - 2)];
                const uint32_t b1 = (j < 2) ? bq[2 * j + 1] : br[2 * (j - 2) + 1];
#pragma unroll
                for (int t = 0; t < 2; t++)
                    asm volatile(
                        "mma.sync.aligned.m16n8k16.row.col.f32.f16.f16.f32 "
                        "{%0,%1,%2,%3}, {%4,%5,%6,%7}, {%8,%9}, {%0,%1,%2,%3};"
                        : "+f"(d[t][j][0]), "+f"(d[t][j][1]),
                          "+f"(d[t][j][2]), "+f"(d[t][j][3])
                        : "r"(a[t][0]), "r"(a[t][1]), "r"(a[t][2]), "r"(a[t][3]),
                          "r"(b0), "r"(b1));
            }
        }

        if (ck == 1) {
#pragma unroll
            for (int t = 0; t < 2; t++) {
                const int xa = 16 * t + grp;
#pragma unroll
                for (int j = 0; j < 4; j++) {
                    const int cgl = n0 + j * 8 + thr4 * 2;
                    int i0 = dv * 8192 + zl * 2048 + xa * 64 + cgl;
                    *(float2*)&sc[i0]          = make_float2(d[t][j][0], d[t][j][1]);
                    *(float2*)&sc[i0 + 8 * 64] = make_float2(d[t][j][2], d[t][j][3]);
                }
            }
        }
        __syncthreads();
    }
#undef STAGE_FILL

    float4* o4 = (float4*)out;
#pragma unroll
    for (int i = 0; i < 32; i++) {
        int f   = i * 256 + tid;
        int c   = f & 63;
        int xa  = (f >> 6) & 31;
        int zz  = f >> 11;
        int p   = zz * 2048 + xa * 64 + c;
        float4 v;
        v.x = sc[p];
        v.y = sc[p + 8192];
        v.z = sc[p + 16384];
        v.w = sc[p + 24576];
        size_t oi = (((size_t)(b * NZ + zq * 4 + zz) * NZ + xq * 32 + xa) * NZ
                     + ch * 64 + c);
        o4[oi] = v;
    }
}

// ---------------------------------------------------------------------------
extern "C" void kernel_launch(void* const* d_in, const int* in_sizes, int n_in,
                              void* d_out, int out_size)
{
    (void)in_sizes; (void)n_in; (void)out_size;
    const float* x1 = (const float*)d_in[0];
    const float* x2 = (const float*)d_in[1];
    const float* x3 = (const float*)d_in[2];
    const float* W1 = (const float*)d_in[3];
    const float* b1 = (const float*)d_in[4];
    const float* W2 = (const float*)d_in[5];
    const float* b2 = (const float*)d_in[6];
    const float* W3 = (const float*)d_in[7];
    const float* b3 = (const float*)d_in[8];
    float* out = (float*)d_out;

    static int attr_done = 0;
    if (!attr_done) {
        cudaFuncSetAttribute(tri_mma_kernel,
                             cudaFuncAttributeMaxDynamicSharedMemorySize, SMEM_BYTES);
        cudaFuncSetAttribute(proj_mma_kernel,
                             cudaFuncAttributeMaxDynamicSharedMemorySize, PROJ_SMEM);
        attr_done = 1;
    }

    proj_mma_kernel<<<dim3(16, NB, 3), 256, PROJ_SMEM>>>(x1, x2, x3, W1, b1, W2, b2, W3, b3);
    tri_mma_kernel<<<dim3(32, 8, NB), 256, SMEM_BYTES>>>(out);
}